// round 17
// baseline (speedup 1.0000x reference)
#include <cuda_runtime.h>
#include <cuda_bf16.h>
#include <cuda_fp16.h>
#include <cstdint>

#define BATCH 8
#define NTOK 4096
#define CH 64
#define NGROUP 8
#define CPG 8
#define EPSV 1e-3f

// Q pre-scale: C^-0.5 * log2(e), so softmax runs in base-2 (ex2 = bare MUFU)
#define QSCALE 0.1803368801111204f
#define ONES16X2 0x3C003C00u   // fp16 {1.0, 1.0}

// scratch (allocation-free rule: device globals)
__device__ float g_h[BATCH * NTOK * CH];
__device__ float g_part[BATCH * NGROUP * 64 * 2];   // [b][g][slice] (sum, sumsq)
__device__ __nv_bfloat16 g_qb[BATCH * NTOK * CH];   // Q bf16 [tok][c], pre-scaled
__device__ __nv_bfloat16 g_kb[BATCH * NTOK * CH];   // K bf16 [tok][c]
__device__ __half g_vt[BATCH * CH * NTOK];          // V^T fp16 [b][c][tok]
__device__ __nv_bfloat16 g_wpt[CH * CH];            // wp^T bf16 [n][k]
__device__ __nv_bfloat16 g_wqkvt[3 * CH * CH];      // [wq|wk|wv]^T bf16 [n][k]

// ============================ PTX helpers (baseline, no 'a' features) ======
__device__ __forceinline__ uint32_t smem_u32(const void* p) {
    uint32_t a;
    asm("{ .reg .u64 t; cvta.to.shared.u64 t, %1; cvt.u32.u64 %0, t; }" : "=r"(a) : "l"(p));
    return a;
}
__device__ __forceinline__ uint32_t cvt_bf16x2(float lo, float hi) {
    uint32_t r;
    asm("cvt.rn.bf16x2.f32 %0, %1, %2;" : "=r"(r) : "f"(hi), "f"(lo));
    return r;
}
__device__ __forceinline__ uint32_t ex2p(float lo, float hi) {
    uint32_t r;
    asm("{\n\t.reg .b32 t;\n\t"
        "cvt.rn.f16x2.f32 t, %1, %2;\n\t"
        "ex2.approx.f16x2 %0, t;\n\t}"
        : "=r"(r) : "f"(hi), "f"(lo));
    return r;
}
__device__ __forceinline__ void ldmx4(uint32_t& r0, uint32_t& r1, uint32_t& r2,
                                      uint32_t& r3, uint32_t addr) {
    asm volatile("ldmatrix.sync.aligned.m8n8.x4.shared.b16 {%0,%1,%2,%3}, [%4];"
                 : "=r"(r0), "=r"(r1), "=r"(r2), "=r"(r3) : "r"(addr));
}
__device__ __forceinline__ void mma16816(float* c, const uint32_t* a,
                                         uint32_t b0, uint32_t b1) {
    asm volatile(
        "mma.sync.aligned.m16n8k16.row.col.f32.bf16.bf16.f32 "
        "{%0,%1,%2,%3}, {%4,%5,%6,%7}, {%8,%9}, {%0,%1,%2,%3};"
        : "+f"(c[0]), "+f"(c[1]), "+f"(c[2]), "+f"(c[3])
        : "r"(a[0]), "r"(a[1]), "r"(a[2]), "r"(a[3]), "r"(b0), "r"(b1));
}
__device__ __forceinline__ void mma16816h(float* c, const uint32_t* a,
                                          uint32_t b0, uint32_t b1) {
    asm volatile(
        "mma.sync.aligned.m16n8k16.row.col.f32.f16.f16.f32 "
        "{%0,%1,%2,%3}, {%4,%5,%6,%7}, {%8,%9}, {%0,%1,%2,%3};"
        : "+f"(c[0]), "+f"(c[1]), "+f"(c[2]), "+f"(c[3])
        : "r"(a[0]), "r"(a[1]), "r"(a[2]), "r"(a[3]), "r"(b0), "r"(b1));
}
__device__ __forceinline__ void cpa16(uint32_t dst, const void* src) {
    asm volatile("cp.async.cg.shared.global [%0], [%1], 16;" :: "r"(dst), "l"(src)
                 : "memory");
}
#define CP_COMMIT() asm volatile("cp.async.commit_group;" ::: "memory")
#define CP_WAIT1() asm volatile("cp.async.wait_group 1;" ::: "memory")
#define CP_WAIT0() asm volatile("cp.async.wait_group 0;" ::: "memory")

// ============================ GroupNorm partial sums (coalesced, 512 CTAs) ==
__global__ void __launch_bounds__(256) gn_sum_kernel(const float* __restrict__ x,
                                                     const float* __restrict__ wq,
                                                     const float* __restrict__ wk,
                                                     const float* __restrict__ wv,
                                                     const float* __restrict__ wp) {
    int b = blockIdx.x >> 6;
    int slice = blockIdx.x & 63;
    int tid = threadIdx.x;
    int w = tid >> 5, lane = tid & 31;

    if (blockIdx.x < 16) {
        int part = blockIdx.x;
        for (int i = part * 256 + tid; i < CH * CH; i += 4096) {
            int n = i >> 6, k = i & 63;
            g_wpt[i] = __float2bfloat16(wp[k * CH + n]);
        }
        const float* W[3] = {wq, wk, wv};
        for (int i = part * 768 + tid; i < (part + 1) * 768; i += 256) {
            int n = i >> 6, k = i & 63;
            g_wqkvt[i] = __float2bfloat16(W[n >> 6][k * CH + (n & 63)]);
        }
    }

    const float* xb = x + (size_t)b * NTOK * CH + (size_t)slice * 64 * CH;
    int c4 = tid & 15;
    int r0 = tid >> 4;

    float s = 0.f, s2 = 0.f;
#pragma unroll
    for (int rr = 0; rr < 64; rr += 16) {
        float4 v = *(const float4*)(xb + (size_t)(rr + r0) * CH + (c4 << 2));
        s += v.x + v.y + v.z + v.w;
        s2 += v.x * v.x + v.y * v.y + v.z * v.z + v.w * v.w;
    }
    s += __shfl_xor_sync(0xffffffffu, s, 1);
    s2 += __shfl_xor_sync(0xffffffffu, s2, 1);
    s += __shfl_xor_sync(0xffffffffu, s, 16);
    s2 += __shfl_xor_sync(0xffffffffu, s2, 16);

    __shared__ float shs[64], shs2[64];
    if (lane < 16 && (lane & 1) == 0) {
        shs[w * 8 + (lane >> 1)] = s;
        shs2[w * 8 + (lane >> 1)] = s2;
    }
    __syncthreads();
    if (tid < 8) {
        float ts = 0.f, t2 = 0.f;
#pragma unroll
        for (int ww = 0; ww < 8; ww++) { ts += shs[ww * 8 + tid]; t2 += shs2[ww * 8 + tid]; }
        int idx = ((b * 8 + tid) * 64 + slice) * 2;
        g_part[idx] = ts;
        g_part[idx + 1] = t2;
    }
}

// ============================ QKV (tensor cores, fused normalize) ===========
__global__ void __launch_bounds__(128) qkv_kernel(const float* __restrict__ x,
                                                  const float* __restrict__ gamma,
                                                  const float* __restrict__ beta,
                                                  const float* __restrict__ bq,
                                                  const float* __restrict__ bk,
                                                  const float* __restrict__ bv) {
    __shared__ __align__(16) uint8_t smA[16384];
    __shared__ __align__(16) uint8_t smW[24576];
    __shared__ float smean[8], srstd[8];
    int tid = threadIdx.x;
    int w = tid >> 5, lane = tid & 31;
    int b = blockIdx.x >> 5;
    size_t base = (size_t)blockIdx.x * 128 * CH;

    if (tid < 8) {
        float ts = 0.f, t2 = 0.f;
#pragma unroll 8
        for (int sl = 0; sl < 64; sl++) {
            ts += g_part[((b * 8 + tid) * 64 + sl) * 2];
            t2 += g_part[((b * 8 + tid) * 64 + sl) * 2 + 1];
        }
        float inv_n = 1.f / (float)(NTOK * CPG);
        float mean = ts * inv_n;
        float var = t2 * inv_n - mean * mean;
        smean[tid] = mean;
        srstd[tid] = rsqrtf(var + EPSV);
    }
    for (int f = tid; f < 1536; f += 128) {
        int r = f >> 3, c = f & 7;
        *(uint4*)(smW + r * 128 + ((c ^ (r & 7)) << 4)) =
            *(const uint4*)(g_wqkvt + (size_t)r * CH + c * 8);
    }
    __syncthreads();

    for (int f = tid; f < 2048; f += 128) {
        int r = f >> 4, c4 = f & 15;
        float4 xv = *(const float4*)(x + base + r * CH + (c4 << 2));
        int g = c4 >> 1;
        float mn = smean[g], rs = srstd[g];
        float vv[4] = {xv.x, xv.y, xv.z, xv.w};
#pragma unroll
        for (int s = 0; s < 4; s++) {
            int c = (c4 << 2) + s;
            vv[s] = (vv[s] - mn) * rs * gamma[c] + beta[c];
        }
        *(float4*)(g_h + base + r * CH + (c4 << 2)) =
            make_float4(vv[0], vv[1], vv[2], vv[3]);
        int ch = c4 >> 1;
        uint32_t* dst = (uint32_t*)(smA + r * 128 + ((ch ^ (r & 7)) << 4) + (c4 & 1) * 8);
        dst[0] = cvt_bf16x2(vv[0], vv[1]);
        dst[1] = cvt_bf16x2(vv[2], vv[3]);
    }
    __syncthreads();

    uint32_t sa = smem_u32(smA), sw = smem_u32(smW);
    int rl = lane & 15;
    uint32_t abase[2];
    abase[0] = sa + (uint32_t)(w * 32 + rl) * 128;
    abase[1] = abase[0] + 16 * 128;
    int bq_ko = (lane >> 4) & 1;
    int bq_half = (lane >> 3) & 1;
    int blrow = lane & 7;

    uint32_t af[2][2][2][4];
#pragma unroll
    for (int kp = 0; kp < 2; kp++)
#pragma unroll
        for (int mt = 0; mt < 2; mt++)
#pragma unroll
            for (int kh = 0; kh < 2; kh++) {
                int ach = (2 * (2 * kp + kh) + (lane >> 4)) ^ (rl & 7);
                ldmx4(af[kp][mt][kh][0], af[kp][mt][kh][1],
                      af[kp][mt][kh][2], af[kp][mt][kh][3],
                      abase[mt] + (ach << 4));
            }

    const float* Bv[3] = {bq, bk, bv};
#pragma unroll
    for (int m = 0; m < 3; m++) {
        float acc[2][8][4];
#pragma unroll
        for (int mt = 0; mt < 2; mt++)
#pragma unroll
            for (int nt = 0; nt < 8; nt++)
#pragma unroll
                for (int j = 0; j < 4; j++) acc[mt][nt][j] = 0.f;

#pragma unroll
        for (int kp = 0; kp < 2; kp++) {
            int kk2 = 2 * kp;
#pragma unroll
            for (int nt = 0; nt < 8; nt++) {
                int br = m * 64 + nt * 8 + blrow;
                int bc = (2 * (kk2 + bq_ko) + bq_half) ^ (br & 7);
                uint32_t b0, b1, b2, b3;
                ldmx4(b0, b1, b2, b3, sw + br * 128 + (bc << 4));
                mma16816(acc[0][nt], af[kp][0][0], b0, b1);
                mma16816(acc[0][nt], af[kp][0][1], b2, b3);
                mma16816(acc[1][nt], af[kp][1][0], b0, b1);
                mma16816(acc[1][nt], af[kp][1][1], b2, b3);
            }
        }

        int cb = 2 * (lane & 3);
#pragma unroll
        for (int mt = 0; mt < 2; mt++) {
            int tok = blockIdx.x * 128 + w * 32 + mt * 16 + (lane >> 2);
#pragma unroll
            for (int nt = 0; nt < 8; nt++) {
                int col = nt * 8 + cb;
                float b0v = Bv[m][col], b1v = Bv[m][col + 1];
                float r00 = acc[mt][nt][0] + b0v, r01 = acc[mt][nt][1] + b1v;
                float r10 = acc[mt][nt][2] + b0v, r11 = acc[mt][nt][3] + b1v;
                if (m == 0) {
                    ((uint32_t*)g_qb)[(size_t)tok * 32 + (col >> 1)] =
                        cvt_bf16x2(r00 * QSCALE, r01 * QSCALE);
                    ((uint32_t*)g_qb)[(size_t)(tok + 8) * 32 + (col >> 1)] =
                        cvt_bf16x2(r10 * QSCALE, r11 * QSCALE);
                } else if (m == 1) {
                    ((uint32_t*)g_kb)[(size_t)tok * 32 + (col >> 1)] = cvt_bf16x2(r00, r01);
                    ((uint32_t*)g_kb)[(size_t)(tok + 8) * 32 + (col >> 1)] = cvt_bf16x2(r10, r11);
                } else {
                    int tl = tok & 4095;
                    __half* vt = g_vt + (size_t)b * CH * NTOK;
                    vt[(size_t)col * NTOK + tl] = __float2half_rn(r00);
                    vt[(size_t)(col + 1) * NTOK + tl] = __float2half_rn(r01);
                    vt[(size_t)col * NTOK + tl + 8] = __float2half_rn(r10);
                    vt[(size_t)(col + 1) * NTOK + tl + 8] = __float2half_rn(r11);
                }
            }
        }
    }
}

// ============================ Attention + fused proj ========================
// 64-query CTAs (one m16 tile per warp), 4 CTAs/SM, single grid wave.
// 64-key double-buffered stages, hoisted Q fragments, fp16 P/V, l = P @ ones.
#define STAGE_BYTES 16384   // K 64x128B + V 64x128B
#define SV_REL 8192
#define QOFF 32768
#define ATTN_SMEM 40960

__global__ void __launch_bounds__(128, 4) attn_kernel(const float* __restrict__ bp,
                                                      float* __restrict__ out) {
    extern __shared__ __align__(16) uint8_t sm[];
    int tid = threadIdx.x;
    int w = tid >> 5, lane = tid & 31;
    int b = blockIdx.y, qt = blockIdx.x;
    uint32_t sb = smem_u32(sm);

    const __nv_bfloat16* gq = g_qb + ((size_t)b * NTOK + qt * 64) * CH;
    const __nv_bfloat16* gk = g_kb + (size_t)b * NTOK * CH;
    const __half* gvt = g_vt + (size_t)b * CH * NTOK;

    auto fill_stage = [&](int stage, int kb) {
        uint32_t sbase = sb + (uint32_t)stage * STAGE_BYTES;
        int f = tid;
#pragma unroll
        for (int u = 0; u < 4; u++, f += 128) {
            int r = f >> 3, c = f & 7;
            cpa16(sbase + r * 128 + ((c ^ (r & 7)) << 4),
                  gk + (size_t)(kb + r) * CH + c * 8);
        }
        f = tid;
#pragma unroll
        for (int u = 0; u < 4; u++, f += 128) {
            int r = f >> 3, c = f & 7;  // r = channel
            cpa16(sbase + SV_REL + r * 128 + ((c ^ (r & 7)) << 4),
                  gvt + (size_t)r * NTOK + kb + c * 8);
        }
        CP_COMMIT();
    };

    fill_stage(0, 0);
    for (int f = tid; f < 512; f += 128) {
        int r = f >> 3, c = f & 7;
        *(uint4*)(sm + QOFF + r * 128 + ((c ^ (r & 7)) << 4)) =
            *(const uint4*)(gq + (size_t)r * CH + c * 8);
    }
    fill_stage(1, 64);
    __syncthreads();

    int rl = lane & 15;
    uint32_t q0 = sb + QOFF + (uint32_t)(w * 16 + rl) * 128;
    int bq_ko = (lane >> 4) & 1;
    int bq_half = (lane >> 3) & 1;
    int blrow = lane & 7;

    uint32_t qf[4][4];
#pragma unroll
    for (int kk = 0; kk < 4; kk++) {
        int ach = (2 * kk + (lane >> 4)) ^ (rl & 7);
        ldmx4(qf[kk][0], qf[kk][1], qf[kk][2], qf[kk][3], q0 + (ach << 4));
    }

    float lsum[4] = {0.f, 0.f, 0.f, 0.f};
    float oc[8][4];
    float sc[8][4];
    uint32_t pfa[4][4];
#pragma unroll
    for (int nt = 0; nt < 8; nt++)
#pragma unroll
        for (int j = 0; j < 4; j++) oc[nt][j] = 0.f;

    for (int kt = 0; kt < 64; kt++) {
        if (kt < 63) CP_WAIT1(); else CP_WAIT0();
        __syncthreads();

        uint32_t skb = sb + (uint32_t)(kt & 1) * STAGE_BYTES;
        uint32_t svb = skb + SV_REL;

        // ---- S = Q K^T ----
#pragma unroll
        for (int nt = 0; nt < 8; nt++)
#pragma unroll
            for (int j = 0; j < 4; j++) sc[nt][j] = 0.f;

#pragma unroll
        for (int kp = 0; kp < 2; kp++) {
            int kk2 = 2 * kp;
#pragma unroll
            for (int nt = 0; nt < 8; nt++) {
                int br = nt * 8 + blrow;
                int bc = (2 * (kk2 + bq_ko) + bq_half) ^ (br & 7);
                uint32_t b0, b1, b2, b3;
                ldmx4(b0, b1, b2, b3, skb + br * 128 + (bc << 4));
                mma16816(sc[nt], qf[kk2], b0, b1);
                mma16816(sc[nt], qf[kk2 + 1], b2, b3);
            }
        }

        // ---- softmax numerator: paired cvt+ex2 -> fp16 P fragments ----
#pragma unroll
        for (int kk = 0; kk < 4; kk++) {
            pfa[kk][0] = ex2p(sc[2 * kk][0], sc[2 * kk][1]);
            pfa[kk][1] = ex2p(sc[2 * kk][2], sc[2 * kk][3]);
            pfa[kk][2] = ex2p(sc[2 * kk + 1][0], sc[2 * kk + 1][1]);
            pfa[kk][3] = ex2p(sc[2 * kk + 1][2], sc[2 * kk + 1][3]);
        }

        // ---- l += P @ ones (tensor pipe) ----
#pragma unroll
        for (int kk = 0; kk < 4; kk++)
            mma16816h(lsum, pfa[kk], ONES16X2, ONES16X2);

        // ---- O += P V (fp16 MMA) ----
#pragma unroll
        for (int kp = 0; kp < 2; kp++) {
            int kk2 = 2 * kp;
#pragma unroll
            for (int nt = 0; nt < 8; nt++) {
                int br = nt * 8 + blrow;
                int bc = (2 * (kk2 + bq_ko) + bq_half) ^ (br & 7);
                uint32_t b0, b1, b2, b3;
                ldmx4(b0, b1, b2, b3, svb + br * 128 + (bc << 4));
                mma16816h(oc[nt], pfa[kk2], b0, b1);
                mma16816h(oc[nt], pfa[kk2 + 1], b2, b3);
            }
        }

        __syncthreads();
        if (kt + 2 < 64) fill_stage(kt & 1, (kt + 2) * 64);
    }

    // ---- fused proj: normalized O -> bf16 A fragments, GEMM vs wp^T ----
    uint32_t pjf[4][4];
    {
        float i0 = 1.f / lsum[0], i1 = 1.f / lsum[2];
#pragma unroll
        for (int kk = 0; kk < 4; kk++) {
            pjf[kk][0] = cvt_bf16x2(oc[2 * kk][0] * i0, oc[2 * kk][1] * i0);
            pjf[kk][1] = cvt_bf16x2(oc[2 * kk][2] * i1, oc[2 * kk][3] * i1);
            pjf[kk][2] = cvt_bf16x2(oc[2 * kk + 1][0] * i0, oc[2 * kk + 1][1] * i0);
            pjf[kk][3] = cvt_bf16x2(oc[2 * kk + 1][2] * i1, oc[2 * kk + 1][3] * i1);
        }
    }

    __syncthreads();
    for (int f = tid; f < 512; f += 128) {
        int r = f >> 3, c = f & 7;
        *(uint4*)(sm + r * 128 + ((c ^ (r & 7)) << 4)) =
            *(const uint4*)(g_wpt + (size_t)r * CH + c * 8);
    }
    __syncthreads();

    float poc[8][4];
#pragma unroll
    for (int nt = 0; nt < 8; nt++)
#pragma unroll
        for (int j = 0; j < 4; j++) poc[nt][j] = 0.f;

#pragma unroll
    for (int kp = 0; kp < 2; kp++) {
        int kk2 = 2 * kp;
#pragma unroll
        for (int nt = 0; nt < 8; nt++) {
            int br = nt * 8 + blrow;
            int bc = (2 * (kk2 + bq_ko) + bq_half) ^ (br & 7);
            uint32_t b0, b1, b2, b3;
            ldmx4(b0, b1, b2, b3, sb + br * 128 + (bc << 4));
            mma16816(poc[nt], pjf[kk2], b0, b1);
            mma16816(poc[nt], pjf[kk2 + 1], b2, b3);
        }
    }

    // ---- store: out = h + proj + bp ----
    const float* gh = g_h + (size_t)b * NTOK * CH;
    float* go = out + (size_t)b * NTOK * CH;
    int cb = 2 * (lane & 3);
    int r0 = qt * 64 + w * 16 + (lane >> 2);
#pragma unroll
    for (int nt = 0; nt < 8; nt++) {
        int col = nt * 8 + cb;
        float bp0 = bp[col], bp1 = bp[col + 1];
        float2 h0 = *(const float2*)(gh + (size_t)r0 * CH + col);
        float2 h1 = *(const float2*)(gh + (size_t)(r0 + 8) * CH + col);
        float2 v0 = make_float2(h0.x + poc[nt][0] + bp0, h0.y + poc[nt][1] + bp1);
        float2 v1 = make_float2(h1.x + poc[nt][2] + bp0, h1.y + poc[nt][3] + bp1);
        *(float2*)(go + (size_t)r0 * CH + col) = v0;
        *(float2*)(go + (size_t)(r0 + 8) * CH + col) = v1;
    }
}

extern "C" void kernel_launch(void* const* d_in, const int* in_sizes, int n_in,
                              void* d_out, int out_size) {
    const float* x     = (const float*)d_in[0];
    const float* gamma = (const float*)d_in[1];
    const float* beta  = (const float*)d_in[2];
    const float* wq    = (const float*)d_in[3];
    const float* bq    = (const float*)d_in[4];
    const float* wk    = (const float*)d_in[5];
    const float* bk    = (const float*)d_in[6];
    const float* wv    = (const float*)d_in[7];
    const float* bv    = (const float*)d_in[8];
    const float* wp    = (const float*)d_in[9];
    const float* bp    = (const float*)d_in[10];
    float* out = (float*)d_out;

    cudaFuncSetAttribute(attn_kernel, cudaFuncAttributeMaxDynamicSharedMemorySize,
                         ATTN_SMEM);

    gn_sum_kernel<<<BATCH * 64, 256>>>(x, wq, wk, wv, wp);
    qkv_kernel<<<BATCH * NTOK / 128, 128>>>(x, gamma, beta, bq, bk, bv);
    attn_kernel<<<dim3(NTOK / 64, BATCH), 128, ATTN_SMEM>>>(bp, out);
}